// round 10
// baseline (speedup 1.0000x reference)
#include <cuda_runtime.h>
#include <cstdint>

// ---------------- problem constants ----------------
#define BATCH   8
#define SEQ     16384
#define CH      128
#define WIN     32
#define STRD    16
#define NB      1023
#define MROWS   (BATCH*NB)           // 8184
#define K1      4096
#define N1      256
#define K2      256
#define N2      128

// ---------------- scratch (__device__ globals; no allocation) ----------------
__device__ float g_b1p[N1];
__device__ float g_partial[32 * N1];
__device__ float g_h[(size_t)MROWS * N1];     // 8.4 MB intermediate
__device__ float g_W1t[(size_t)N1 * K1];      // 4 MB transposed + rounded + pair-permuted W1

// ---------------- helpers ----------------
__device__ __forceinline__ uint32_t cvt_tf32(float x) {
    uint32_t u; asm("cvt.rna.tf32.f32 %0, %1;" : "=r"(u) : "f"(x)); return u;
}
__device__ __forceinline__ float rna_tf32_f(float x) {
    uint32_t u = cvt_tf32(x); return __uint_as_float(u);
}
__device__ __forceinline__ void mma_tf32(float c[4], const uint32_t a[4], const uint32_t b[2]) {
    asm volatile(
        "mma.sync.aligned.m16n8k8.row.col.f32.tf32.tf32.f32 "
        "{%0,%1,%2,%3}, {%4,%5,%6,%7}, {%8,%9}, {%0,%1,%2,%3};"
        : "+f"(c[0]), "+f"(c[1]), "+f"(c[2]), "+f"(c[3])
        : "r"(a[0]), "r"(a[1]), "r"(a[2]), "r"(a[3]), "r"(b[0]), "r"(b[1]));
}
__device__ __forceinline__ void cp_async16(uint32_t dst, const void* src) {
    asm volatile("cp.async.cg.shared.global [%0], [%1], 16;" :: "r"(dst), "l"(src));
}
__device__ __forceinline__ void cp_commit() {
    asm volatile("cp.async.commit_group;");
}
__device__ __forceinline__ float gelu_exact(float v) {
    return 0.5f * v * (1.0f + erff(v * 0.70710678118654752f));
}

// ---------------- pre-kernels ----------------
__global__ void pos_w1_partial(const float* __restrict__ pos, const float* __restrict__ W1) {
    int kc = blockIdx.x;
    int n  = threadIdx.x;
    int k0 = kc * 128;
    float s = 0.f;
    #pragma unroll 4
    for (int k = 0; k < 128; k++)
        s += pos[k0 + k] * W1[(size_t)(k0 + k) * N1 + n];
    g_partial[kc * N1 + n] = s;
}
__global__ void pos_w1_reduce(const float* __restrict__ b1) {
    int n = threadIdx.x;
    float s = b1[n];
    #pragma unroll
    for (int i = 0; i < 32; i++) s += g_partial[i * N1 + n];
    g_b1p[n] = s;
}
// W1 (K1,N1) -> g_W1t (N1,K1): transposed, tf32-rna-rounded, pair-permuted
// within each 8-k group: out position 2j+h holds k = j + 4h, so an LDS.64 at
// pair offset qc yields (k=qc, k=qc+4) = the mma B fragment.
__global__ void transpose_w1(const float* __restrict__ W1) {
    __shared__ float tile[32][33];
    int k0 = blockIdx.x * 32, n0 = blockIdx.y * 32;
    int tx = threadIdx.x, ty = threadIdx.y;   // 32 x 8
    #pragma unroll
    for (int i = 0; i < 32; i += 8)
        tile[ty + i][tx] = W1[(size_t)(k0 + ty + i) * N1 + n0 + tx];
    __syncthreads();
    int ko = tx >> 3;
    int r  = tx & 7;
    int j  = r >> 1;
    int h  = r & 1;
    int ksrc = ko * 8 + j + 4 * h;
    #pragma unroll
    for (int i = 0; i < 32; i += 8)
        g_W1t[(size_t)(n0 + ty + i) * K1 + k0 + tx] = rna_tf32_f(tile[ksrc][ty + i]);
}

// ================= kernel 1: h = gelu(gather(x) @ W1 + b1') =================
// BM=128, BN=128, BK=64. Grid 64 x 2 = 128 CTAs. 512 threads / 16 warps.
// Warp grid 4M x 4N; warp tile 32x32; Mfrag=2, Nfrag=4.
// A smem: 128 x 68 (LDS.32 frags, conflict-free: 68 mod 32 = 4).
// B smem: 128 x 72, pair-permuted k (LDS.64 frags, conflict-free: 288B row).
#define K1_BM     128
#define K1_BN     128
#define K1_BK     64
#define K1_ASTR   68
#define K1_BSTR   72
#define K1_AELE   (K1_BM * K1_ASTR)   // 8704
#define K1_BELE   (K1_BN * K1_BSTR)   // 9216
#define K1_STAGE  (K1_AELE + K1_BELE) // 17920 floats
#define K1_STAGES 3
#define K1_SMEM   (K1_STAGES * K1_STAGE * 4)   // 215040 B
#define K1_NCHUNK (K1 / K1_BK)                 // 64

__global__ __launch_bounds__(512, 1)
void k1_gemm_gelu(const float* __restrict__ x) {
    extern __shared__ float smem[];

    const int tid   = threadIdx.x;
    const int lane  = tid & 31;
    const int warp  = tid >> 5;
    const int warpM = warp >> 2;      // 0..3  (32 rows)
    const int warpN = warp & 3;       // 0..3  (32 cols)
    const int qr    = lane >> 2;      // 0..7
    const int qc    = lane & 3;       // 0..3
    const int mtile = blockIdx.x;     // 0..63
    const int ntile = blockIdx.y;     // 0..1

    // ---- loaders: 4 threads/row; each thread 4 A chunks + 4 B chunks (16B) ----
    const int lrow = tid >> 2;            // 0..127
    const int lq   = (tid & 3) * 4;       // chunk base 0,4,8,12 (of 16 per row)
    int m  = mtile * K1_BM + lrow;
    int mc = (m < MROWS) ? m : (MROWS - 1);
    int bb = mc / NB;
    const float* arow_base = x + ((size_t)bb * SEQ + (size_t)(mc - bb * NB) * STRD) * CH;
    const float* brow_base = g_W1t + (size_t)(ntile * K1_BN + lrow) * K1;

    auto load_chunk = [&](int kc) {
        float* As = smem + (kc % K1_STAGES) * K1_STAGE;
        float* Bs = As + K1_AELE;
        const int t   = kc >> 1;              // token (64 k = half a token's 128 ch)
        const int ch0 = (kc & 1) * 64;
        const float* asrc = arow_base + t * CH + ch0;
        const float* bsrc = brow_base + kc * K1_BK;
        #pragma unroll
        for (int i = 0; i < 4; i++) {
            int ck = lq + i;
            cp_async16((uint32_t)__cvta_generic_to_shared(As + lrow * K1_ASTR + ck * 4),
                       asrc + ck * 4);
            cp_async16((uint32_t)__cvta_generic_to_shared(Bs + lrow * K1_BSTR + ck * 4),
                       bsrc + ck * 4);
        }
        cp_commit();
    };

    float acc[2][4][4];
    #pragma unroll
    for (int a = 0; a < 2; a++)
        #pragma unroll
        for (int b = 0; b < 4; b++)
            #pragma unroll
            for (int c = 0; c < 4; c++) acc[a][b][c] = 0.f;

    load_chunk(0);
    load_chunk(1);

    for (int kc = 0; kc < K1_NCHUNK; kc++) {
        if (kc + 1 < K1_NCHUNK) asm volatile("cp.async.wait_group 1;");
        else                    asm volatile("cp.async.wait_group 0;");
        __syncthreads();
        if (kc + 2 < K1_NCHUNK) load_chunk(kc + 2);

        const float* As = smem + (kc % K1_STAGES) * K1_STAGE;
        const float* Bs = As + K1_AELE;
        #pragma unroll
        for (int ks = 0; ks < 8; ks++) {
            uint32_t af[2][4];
            #pragma unroll
            for (int mi = 0; mi < 2; mi++) {
                int r0 = warpM * 32 + mi * 16 + qr;
                af[mi][0] = cvt_tf32(As[ r0      * K1_ASTR + ks * 8 + qc    ]);
                af[mi][1] = cvt_tf32(As[(r0 + 8) * K1_ASTR + ks * 8 + qc    ]);
                af[mi][2] = cvt_tf32(As[ r0      * K1_ASTR + ks * 8 + qc + 4]);
                af[mi][3] = cvt_tf32(As[(r0 + 8) * K1_ASTR + ks * 8 + qc + 4]);
            }
            #pragma unroll
            for (int ni = 0; ni < 4; ni++) {
                int n = warpN * 32 + ni * 8 + qr;
                // pair-permuted layout: one aligned 64-bit load = (k=qc, k=qc+4)
                float2 bp = *(const float2*)(Bs + n * K1_BSTR + ks * 8 + qc * 2);
                uint32_t bf[2];
                bf[0] = __float_as_uint(bp.x);   // pre-rounded bits
                bf[1] = __float_as_uint(bp.y);
                #pragma unroll
                for (int mi = 0; mi < 2; mi++)
                    mma_tf32(acc[mi][ni], af[mi], bf);
            }
        }
    }

    // ---- epilogue: bias + exact GELU -> g_h ----
    #pragma unroll
    for (int ni = 0; ni < 4; ni++) {
        int col = ntile * K1_BN + warpN * 32 + ni * 8 + qc * 2;
        float bs0 = g_b1p[col], bs1 = g_b1p[col + 1];
        #pragma unroll
        for (int mi = 0; mi < 2; mi++) {
            #pragma unroll
            for (int half = 0; half < 2; half++) {
                int mm = mtile * K1_BM + warpM * 32 + mi * 16 + qr + half * 8;
                if (mm < MROWS) {
                    float v0 = gelu_exact(acc[mi][ni][half * 2 + 0] + bs0);
                    float v1 = gelu_exact(acc[mi][ni][half * 2 + 1] + bs1);
                    *(float2*)(g_h + (size_t)mm * N1 + col) = make_float2(v0, v1);
                }
            }
        }
    }
}

// ================= kernel 2: out = h @ W2 + b2 =================
// BM=64, BN=128, BK=32. Grid 128 CTAs.
#define K2_BM    64
#define K2_BN    128
#define K2_ASTR  36
#define K2_BSTR  136
#define K2_AELE  (K2_BM * K2_ASTR)    // 2304
#define K2_BELE  (32 * K2_BSTR)       // 4352
#define K2_STAGE (K2_AELE + K2_BELE)  // 6656 floats
#define K2_STAGES 3
#define K2_SMEM  (K2_STAGES * K2_STAGE * 4)   // 79872 B
#define K2_NCHUNK (K2 / 32)                   // 8

__global__ __launch_bounds__(256, 1)
void k2_gemm(const float* __restrict__ W2, const float* __restrict__ b2,
             float* __restrict__ out) {
    extern __shared__ float smem[];

    const int tid   = threadIdx.x;
    const int lane  = tid & 31;
    const int warp  = tid >> 5;
    const int warpM = warp >> 2;      // 0..1 (32 rows)
    const int warpN = warp & 3;       // 0..3 (32 cols)
    const int qr    = lane >> 2;
    const int qc    = lane & 3;
    const int mtile = blockIdx.x;     // 0..127

    const int arow = tid >> 2;        // 0..63
    const int ach2 = (tid & 3) * 2;
    int m0 = mtile * K2_BM + arow;
    const int mrow = (m0 < MROWS) ? m0 : (MROWS - 1);
    const int bkrow = tid >> 5;       // 0..7
    const int bcol4 = tid & 31;       // 0..31

    auto load_chunk = [&](int kc) {
        float* As = smem + (kc % K2_STAGES) * K2_STAGE;
        float* Bs = As + K2_AELE;
        #pragma unroll
        for (int i = 0; i < 2; i++) {
            int ck = ach2 + i;
            cp_async16((uint32_t)__cvta_generic_to_shared(As + arow * K2_ASTR + ck * 4),
                       g_h + (size_t)mrow * K2 + kc * 32 + ck * 4);
        }
        #pragma unroll
        for (int i = 0; i < 4; i++) {
            int kr = bkrow + i * 8;
            cp_async16((uint32_t)__cvta_generic_to_shared(Bs + kr * K2_BSTR + bcol4 * 4),
                       W2 + (size_t)(kc * 32 + kr) * N2 + bcol4 * 4);
        }
        cp_commit();
    };

    float acc[2][4][4];
    #pragma unroll
    for (int a = 0; a < 2; a++)
        #pragma unroll
        for (int b = 0; b < 4; b++)
            #pragma unroll
            for (int c = 0; c < 4; c++) acc[a][b][c] = 0.f;

    load_chunk(0);
    load_chunk(1);

    for (int kc = 0; kc < K2_NCHUNK; kc++) {
        if (kc + 1 < K2_NCHUNK) asm volatile("cp.async.wait_group 1;");
        else                    asm volatile("cp.async.wait_group 0;");
        __syncthreads();
        if (kc + 2 < K2_NCHUNK) load_chunk(kc + 2);

        const float* As = smem + (kc % K2_STAGES) * K2_STAGE;
        const float* Bs = As + K2_AELE;
        #pragma unroll
        for (int ks = 0; ks < 4; ks++) {
            uint32_t af[2][4];
            #pragma unroll
            for (int mi = 0; mi < 2; mi++) {
                int r0 = warpM * 32 + mi * 16 + qr;
                af[mi][0] = cvt_tf32(As[ r0      * K2_ASTR + ks * 8 + qc    ]);
                af[mi][1] = cvt_tf32(As[(r0 + 8) * K2_ASTR + ks * 8 + qc    ]);
                af[mi][2] = cvt_tf32(As[ r0      * K2_ASTR + ks * 8 + qc + 4]);
                af[mi][3] = cvt_tf32(As[(r0 + 8) * K2_ASTR + ks * 8 + qc + 4]);
            }
            #pragma unroll
            for (int ni = 0; ni < 4; ni++) {
                int c0 = warpN * 32 + ni * 8 + qr;
                uint32_t bf[2];
                bf[0] = cvt_tf32(Bs[(ks * 8 + qc    ) * K2_BSTR + c0]);
                bf[1] = cvt_tf32(Bs[(ks * 8 + qc + 4) * K2_BSTR + c0]);
                #pragma unroll
                for (int mi = 0; mi < 2; mi++)
                    mma_tf32(acc[mi][ni], af[mi], bf);
            }
        }
    }

    #pragma unroll
    for (int ni = 0; ni < 4; ni++) {
        int col = warpN * 32 + ni * 8 + qc * 2;
        float bs0 = b2[col], bs1 = b2[col + 1];
        #pragma unroll
        for (int mi = 0; mi < 2; mi++) {
            #pragma unroll
            for (int half = 0; half < 2; half++) {
                int mm = mtile * K2_BM + warpM * 32 + mi * 16 + qr + half * 8;
                if (mm < MROWS) {
                    float v0 = acc[mi][ni][half * 2 + 0] + bs0;
                    float v1 = acc[mi][ni][half * 2 + 1] + bs1;
                    *(float2*)(out + (size_t)mm * N2 + col) = make_float2(v0, v1);
                }
            }
        }
    }
}

// ---------------- launch ----------------
extern "C" void kernel_launch(void* const* d_in, const int* in_sizes, int n_in,
                              void* d_out, int out_size) {
    const float* x   = (const float*)d_in[0];
    const float* pos = (const float*)d_in[1];
    const float* W1  = (const float*)d_in[2];
    const float* b1  = (const float*)d_in[3];
    const float* W2  = (const float*)d_in[4];
    const float* b2  = (const float*)d_in[5];
    float* out = (float*)d_out;

    cudaFuncSetAttribute(k1_gemm_gelu, cudaFuncAttributeMaxDynamicSharedMemorySize, K1_SMEM);
    cudaFuncSetAttribute(k2_gemm,      cudaFuncAttributeMaxDynamicSharedMemorySize, K2_SMEM);

    dim3 tb(32, 8);
    transpose_w1<<<dim3(K1 / 32, N1 / 32), tb>>>(W1);
    pos_w1_partial<<<32, 256>>>(pos, W1);
    pos_w1_reduce<<<1, 256>>>(b1);

    dim3 g1(64, 2);                    // 128 CTAs, 512 threads each
    k1_gemm_gelu<<<g1, 512, K1_SMEM>>>(x);

    k2_gemm<<<128, 256, K2_SMEM>>>(W2, b2, out);
}

// round 11
// speedup vs baseline: 1.3265x; 1.3265x over previous
#include <cuda_runtime.h>
#include <cstdint>

// ---------------- problem constants ----------------
#define BATCH   8
#define SEQ     16384
#define CH      128
#define WIN     32
#define STRD    16
#define NB      1023
#define MROWS   (BATCH*NB)           // 8184
#define K1      4096
#define N1      256
#define K2      256
#define N2      128

// ---------------- scratch (__device__ globals; no allocation) ----------------
__device__ float g_b1p[N1];
__device__ float g_partial[32 * N1];
__device__ float g_h[(size_t)MROWS * N1];     // 8.4 MB intermediate

// ---------------- helpers ----------------
__device__ __forceinline__ uint32_t cvt_tf32(float x) {
    uint32_t u; asm("cvt.rna.tf32.f32 %0, %1;" : "=r"(u) : "f"(x)); return u;
}
__device__ __forceinline__ void mma_tf32(float c[4], const uint32_t a[4], const uint32_t b[2]) {
    asm volatile(
        "mma.sync.aligned.m16n8k8.row.col.f32.tf32.tf32.f32 "
        "{%0,%1,%2,%3}, {%4,%5,%6,%7}, {%8,%9}, {%0,%1,%2,%3};"
        : "+f"(c[0]), "+f"(c[1]), "+f"(c[2]), "+f"(c[3])
        : "r"(a[0]), "r"(a[1]), "r"(a[2]), "r"(a[3]), "r"(b[0]), "r"(b[1]));
}
__device__ __forceinline__ void cp_async16(uint32_t dst, const void* src) {
    asm volatile("cp.async.cg.shared.global [%0], [%1], 16;" :: "r"(dst), "l"(src));
}
__device__ __forceinline__ void cp_commit() {
    asm volatile("cp.async.commit_group;");
}
__device__ __forceinline__ float gelu_exact(float v) {
    return 0.5f * v * (1.0f + erff(v * 0.70710678118654752f));
}

// ---------------- pre-kernels: b1' = b1 + pos_flat @ W1 ----------------
__global__ void pos_w1_partial(const float* __restrict__ pos, const float* __restrict__ W1) {
    int kc = blockIdx.x;
    int n  = threadIdx.x;
    int k0 = kc * 128;
    float s = 0.f;
    #pragma unroll 4
    for (int k = 0; k < 128; k++)
        s += pos[k0 + k] * W1[(size_t)(k0 + k) * N1 + n];
    g_partial[kc * N1 + n] = s;
}
__global__ void pos_w1_reduce(const float* __restrict__ b1) {
    int n = threadIdx.x;
    float s = b1[n];
    #pragma unroll
    for (int i = 0; i < 32; i++) s += g_partial[i * N1 + n];
    g_b1p[n] = s;
}

// ================= kernel 1: h = gelu(gather(x) @ W1 + b1') =================
// BM=64, BN=128, BK=32. Grid 128 x 2 = 256 CTAs, 256 threads, 2 CTAs/SM.
// Two independent CTAs per SM desynchronize barrier phases and hide latency.
// Warp grid 2M x 4N; warp tile 32x32 (Mfrag=2, Nfrag=4).
#define K1_BM    64
#define K1_BN    128
#define K1_ASTR  36
#define K1_BSTR  136
#define K1_AELE  (K1_BM * K1_ASTR)    // 2304
#define K1_BELE  (32 * K1_BSTR)       // 4352
#define K1_STAGE (K1_AELE + K1_BELE)  // 6656 floats
#define K1_STAGES 3
#define K1_SMEM  (K1_STAGES * K1_STAGE * 4)   // 79872 B -> 2 CTAs/SM
#define K1_NCHUNK (K1 / 32)                   // 128

__global__ __launch_bounds__(256, 2)
void k1_gemm_gelu(const float* __restrict__ x, const float* __restrict__ W1) {
    extern __shared__ float smem[];

    const int tid   = threadIdx.x;
    const int lane  = tid & 31;
    const int warp  = tid >> 5;
    const int warpM = warp >> 2;      // 0..1 (32 rows)
    const int warpN = warp & 3;       // 0..3 (32 cols)
    const int qr    = lane >> 2;      // 0..7
    const int qc    = lane & 3;       // 0..3
    const int mtile = blockIdx.x;     // 0..127
    const int ntile = blockIdx.y;     // 0..1

    // ---- A loader (gather): 64 rows, 4 threads/row, 2 16B-chunks each ----
    const int arow = tid >> 2;        // 0..63
    const int ach2 = (tid & 3) * 2;   // chunk base 0,2,4,6
    int m  = mtile * K1_BM + arow;
    int mc = (m < MROWS) ? m : (MROWS - 1);   // clamp; stores predicated
    int bb = mc / NB;
    const float* arow_base = x + ((size_t)bb * SEQ + (size_t)(mc - bb * NB) * STRD) * CH;
    // ---- B loader: 32 k-rows x 128 n, 8 rows of threads, 4 k-rows each ----
    const int bkrow = tid >> 5;       // 0..7
    const int bcol4 = tid & 31;       // 0..31

    auto load_chunk = [&](int kc) {
        float* As = smem + (kc % K1_STAGES) * K1_STAGE;
        float* Bs = As + K1_AELE;
        const int t   = kc >> 2;              // token within window
        const int ch0 = (kc & 3) * 32;        // channel base
        #pragma unroll
        for (int i = 0; i < 2; i++) {
            int ck = ach2 + i;
            cp_async16((uint32_t)__cvta_generic_to_shared(As + arow * K1_ASTR + ck * 4),
                       arow_base + t * CH + ch0 + ck * 4);
        }
        #pragma unroll
        for (int i = 0; i < 4; i++) {
            int kr = bkrow + i * 8;
            cp_async16((uint32_t)__cvta_generic_to_shared(Bs + kr * K1_BSTR + bcol4 * 4),
                       W1 + (size_t)(kc * 32 + kr) * N1 + ntile * K1_BN + bcol4 * 4);
        }
        cp_commit();
    };

    float acc[2][4][4];
    #pragma unroll
    for (int a = 0; a < 2; a++)
        #pragma unroll
        for (int b = 0; b < 4; b++)
            #pragma unroll
            for (int c = 0; c < 4; c++) acc[a][b][c] = 0.f;

    load_chunk(0);
    load_chunk(1);

    for (int kc = 0; kc < K1_NCHUNK; kc++) {
        if (kc + 1 < K1_NCHUNK) asm volatile("cp.async.wait_group 1;");
        else                    asm volatile("cp.async.wait_group 0;");
        __syncthreads();
        if (kc + 2 < K1_NCHUNK) load_chunk(kc + 2);

        const float* As = smem + (kc % K1_STAGES) * K1_STAGE;
        const float* Bs = As + K1_AELE;
        #pragma unroll
        for (int ks = 0; ks < 4; ks++) {
            uint32_t af[2][4];
            #pragma unroll
            for (int mi = 0; mi < 2; mi++) {
                int r0 = warpM * 32 + mi * 16 + qr;
                af[mi][0] = cvt_tf32(As[ r0      * K1_ASTR + ks * 8 + qc    ]);
                af[mi][1] = cvt_tf32(As[(r0 + 8) * K1_ASTR + ks * 8 + qc    ]);
                af[mi][2] = cvt_tf32(As[ r0      * K1_ASTR + ks * 8 + qc + 4]);
                af[mi][3] = cvt_tf32(As[(r0 + 8) * K1_ASTR + ks * 8 + qc + 4]);
            }
            #pragma unroll
            for (int ni = 0; ni < 4; ni++) {
                int c0 = warpN * 32 + ni * 8 + qr;
                uint32_t bf[2];
                bf[0] = cvt_tf32(Bs[(ks * 8 + qc    ) * K1_BSTR + c0]);
                bf[1] = cvt_tf32(Bs[(ks * 8 + qc + 4) * K1_BSTR + c0]);
                #pragma unroll
                for (int mi = 0; mi < 2; mi++)
                    mma_tf32(acc[mi][ni], af[mi], bf);
            }
        }
    }

    // ---- epilogue: bias + exact GELU -> g_h ----
    #pragma unroll
    for (int ni = 0; ni < 4; ni++) {
        int col = ntile * K1_BN + warpN * 32 + ni * 8 + qc * 2;
        float bs0 = g_b1p[col], bs1 = g_b1p[col + 1];
        #pragma unroll
        for (int mi = 0; mi < 2; mi++) {
            #pragma unroll
            for (int half = 0; half < 2; half++) {
                int mm = mtile * K1_BM + warpM * 32 + mi * 16 + qr + half * 8;
                if (mm < MROWS) {
                    float v0 = gelu_exact(acc[mi][ni][half * 2 + 0] + bs0);
                    float v1 = gelu_exact(acc[mi][ni][half * 2 + 1] + bs1);
                    *(float2*)(g_h + (size_t)mm * N1 + col) = make_float2(v0, v1);
                }
            }
        }
    }
}

// ================= kernel 2: out = h @ W2 + b2 =================
// BM=64, BN=128, BK=32. Grid 128 CTAs. (proven, unchanged)
#define K2_BM    64
#define K2_BN    128
#define K2_ASTR  36
#define K2_BSTR  136
#define K2_AELE  (K2_BM * K2_ASTR)    // 2304
#define K2_BELE  (32 * K2_BSTR)       // 4352
#define K2_STAGE (K2_AELE + K2_BELE)  // 6656 floats
#define K2_STAGES 3
#define K2_SMEM  (K2_STAGES * K2_STAGE * 4)   // 79872 B
#define K2_NCHUNK (K2 / 32)                   // 8

__global__ __launch_bounds__(256, 2)
void k2_gemm(const float* __restrict__ W2, const float* __restrict__ b2,
             float* __restrict__ out) {
    extern __shared__ float smem[];

    const int tid   = threadIdx.x;
    const int lane  = tid & 31;
    const int warp  = tid >> 5;
    const int warpM = warp >> 2;      // 0..1 (32 rows)
    const int warpN = warp & 3;       // 0..3 (32 cols)
    const int qr    = lane >> 2;
    const int qc    = lane & 3;
    const int mtile = blockIdx.x;     // 0..127

    const int arow = tid >> 2;        // 0..63
    const int ach2 = (tid & 3) * 2;
    int m0 = mtile * K2_BM + arow;
    const int mrow = (m0 < MROWS) ? m0 : (MROWS - 1);
    const int bkrow = tid >> 5;       // 0..7
    const int bcol4 = tid & 31;       // 0..31

    auto load_chunk = [&](int kc) {
        float* As = smem + (kc % K2_STAGES) * K2_STAGE;
        float* Bs = As + K2_AELE;
        #pragma unroll
        for (int i = 0; i < 2; i++) {
            int ck = ach2 + i;
            cp_async16((uint32_t)__cvta_generic_to_shared(As + arow * K2_ASTR + ck * 4),
                       g_h + (size_t)mrow * K2 + kc * 32 + ck * 4);
        }
        #pragma unroll
        for (int i = 0; i < 4; i++) {
            int kr = bkrow + i * 8;
            cp_async16((uint32_t)__cvta_generic_to_shared(Bs + kr * K2_BSTR + bcol4 * 4),
                       W2 + (size_t)(kc * 32 + kr) * N2 + bcol4 * 4);
        }
        cp_commit();
    };

    float acc[2][4][4];
    #pragma unroll
    for (int a = 0; a < 2; a++)
        #pragma unroll
        for (int b = 0; b < 4; b++)
            #pragma unroll
            for (int c = 0; c < 4; c++) acc[a][b][c] = 0.f;

    load_chunk(0);
    load_chunk(1);

    for (int kc = 0; kc < K2_NCHUNK; kc++) {
        if (kc + 1 < K2_NCHUNK) asm volatile("cp.async.wait_group 1;");
        else                    asm volatile("cp.async.wait_group 0;");
        __syncthreads();
        if (kc + 2 < K2_NCHUNK) load_chunk(kc + 2);

        const float* As = smem + (kc % K2_STAGES) * K2_STAGE;
        const float* Bs = As + K2_AELE;
        #pragma unroll
        for (int ks = 0; ks < 4; ks++) {
            uint32_t af[2][4];
            #pragma unroll
            for (int mi = 0; mi < 2; mi++) {
                int r0 = warpM * 32 + mi * 16 + qr;
                af[mi][0] = cvt_tf32(As[ r0      * K2_ASTR + ks * 8 + qc    ]);
                af[mi][1] = cvt_tf32(As[(r0 + 8) * K2_ASTR + ks * 8 + qc    ]);
                af[mi][2] = cvt_tf32(As[ r0      * K2_ASTR + ks * 8 + qc + 4]);
                af[mi][3] = cvt_tf32(As[(r0 + 8) * K2_ASTR + ks * 8 + qc + 4]);
            }
            #pragma unroll
            for (int ni = 0; ni < 4; ni++) {
                int c0 = warpN * 32 + ni * 8 + qr;
                uint32_t bf[2];
                bf[0] = cvt_tf32(Bs[(ks * 8 + qc    ) * K2_BSTR + c0]);
                bf[1] = cvt_tf32(Bs[(ks * 8 + qc + 4) * K2_BSTR + c0]);
                #pragma unroll
                for (int mi = 0; mi < 2; mi++)
                    mma_tf32(acc[mi][ni], af[mi], bf);
            }
        }
    }

    #pragma unroll
    for (int ni = 0; ni < 4; ni++) {
        int col = warpN * 32 + ni * 8 + qc * 2;
        float bs0 = b2[col], bs1 = b2[col + 1];
        #pragma unroll
        for (int mi = 0; mi < 2; mi++) {
            #pragma unroll
            for (int half = 0; half < 2; half++) {
                int mm = mtile * K2_BM + warpM * 32 + mi * 16 + qr + half * 8;
                if (mm < MROWS) {
                    float v0 = acc[mi][ni][half * 2 + 0] + bs0;
                    float v1 = acc[mi][ni][half * 2 + 1] + bs1;
                    *(float2*)(out + (size_t)mm * N2 + col) = make_float2(v0, v1);
                }
            }
        }
    }
}

// ---------------- launch ----------------
extern "C" void kernel_launch(void* const* d_in, const int* in_sizes, int n_in,
                              void* d_out, int out_size) {
    const float* x   = (const float*)d_in[0];
    const float* pos = (const float*)d_in[1];
    const float* W1  = (const float*)d_in[2];
    const float* b1  = (const float*)d_in[3];
    const float* W2  = (const float*)d_in[4];
    const float* b2  = (const float*)d_in[5];
    float* out = (float*)d_out;

    cudaFuncSetAttribute(k1_gemm_gelu, cudaFuncAttributeMaxDynamicSharedMemorySize, K1_SMEM);
    cudaFuncSetAttribute(k2_gemm,      cudaFuncAttributeMaxDynamicSharedMemorySize, K2_SMEM);

    pos_w1_partial<<<32, 256>>>(pos, W1);
    pos_w1_reduce<<<1, 256>>>(b1);

    dim3 g1(128, 2);                   // 256 CTAs, 2 per SM
    k1_gemm_gelu<<<g1, 256, K1_SMEM>>>(x, W1);

    k2_gemm<<<128, 256, K2_SMEM>>>(W2, b2, out);
}